// round 1
// baseline (speedup 1.0000x reference)
#include <cuda_runtime.h>
#include <cuda_bf16.h>

#define NN 25000
#define NR 16
#define NH 64
#define NC 16
#define NE 800000

// ---- scratch (allocation-free: __device__ globals) ----
__device__ float g_x[NN * NH];                 // acc1 -> relu(x)
__device__ float g_h[(size_t)NR * NN * NC];    // per-relation transformed nodes
__device__ float g_acc2[NN * NC];              // layer-2 aggregation
__device__ int   g_rowidx[NE];                 // rel*NN + src  (row into W1 and into h)
__device__ int   g_dst[NE];
__device__ int   g_is64;

// ---------------------------------------------------------------------------
// Detect whether edge_index arrived as int64 or int32 (jax x64 ambiguity).
// Node ids < 25000, so true int64 data has all high-32 words zero; int32 data
// reinterpreted as u64 has other indices in the high half (P[all zero] ~ 0).
__global__ void k_detect(const void* ei) {
    const unsigned long long* p = (const unsigned long long*)ei;
    unsigned long long acc = 0;
#pragma unroll
    for (int i = 0; i < 64; i++) acc |= (p[i] >> 32);
    g_is64 = (acc == 0ull) ? 1 : 0;
}

// Convert edge metadata once into packed int arrays.
__global__ void k_convert(const void* ei, const void* et) {
    int e = blockIdx.x * blockDim.x + threadIdx.x;
    if (e >= NE) return;
    int src, dst, r;
    if (g_is64) {
        const long long* E = (const long long*)ei;
        const long long* T = (const long long*)et;
        src = (int)E[e]; dst = (int)E[NE + e]; r = (int)T[e];
    } else {
        const int* E = (const int*)ei;
        const int* T = (const int*)et;
        src = E[e]; dst = E[NE + e]; r = T[e];
    }
    g_rowidx[e] = r * NN + src;
    g_dst[e]    = dst;
}

// acc1 = root1 + b1 ; acc2 = 0
__global__ void k_init(const float* __restrict__ root1, const float* __restrict__ b1) {
    int i = blockIdx.x * blockDim.x + threadIdx.x;
    if (i < NN * NH) g_x[i] = root1[i] + b1[i & (NH - 1)];
    if (i < NN * NC) g_acc2[i] = 0.0f;
}

__device__ __forceinline__ void red_add_v4(float* p, float4 v) {
    unsigned long long ga = (unsigned long long)__cvta_generic_to_global((void*)p);
    asm volatile("red.global.add.v4.f32 [%0], {%1,%2,%3,%4};"
                 :: "l"(ga), "f"(v.x), "f"(v.y), "f"(v.z), "f"(v.w) : "memory");
}

// Layer-1 edge pass: acc1[dst] += W1[rel, src].  16 threads per edge (16B each).
__global__ void k_edge1(const float* __restrict__ W1) {
    long gid = (long)blockIdx.x * blockDim.x + threadIdx.x;
    int e = (int)(gid >> 4);
    int s = (int)(gid & 15);
    if (e >= NE) return;
    int row = g_rowidx[e];
    int dst = g_dst[e];
    const float4* w = (const float4*)(W1 + (long)row * NH);
    float4 v = __ldg(&w[s]);
    red_add_v4(g_x + (long)dst * NH + s * 4, v);
}

// ReLU in place (x becomes layer-1 output)
__global__ void k_relu() {
    int i = blockIdx.x * blockDim.x + threadIdx.x;
    if (i < NN * NH) g_x[i] = fmaxf(g_x[i], 0.0f);
}

// h[r, n, c] = sum_h x[n,h] * W2[r,h,c].  grid = (nodeTiles, NR).
// 256 threads = 16 nodes/block; lane c in [0,16), half-warp per node.
__global__ void k_h(const float* __restrict__ W2) {
    __shared__ float w2s[NH * NC];  // 4 KB: W2[r]
    int r = blockIdx.y;
    for (int i = threadIdx.x; i < NH * NC; i += blockDim.x)
        w2s[i] = W2[(long)r * NH * NC + i];
    __syncthreads();

    int c = threadIdx.x & 15;
    int n = blockIdx.x * 16 + (threadIdx.x >> 4);
    if (n >= NN) return;

    const float4* xr = (const float4*)(g_x + (long)n * NH);
    float acc = 0.0f;
#pragma unroll
    for (int h4 = 0; h4 < NH / 4; h4++) {
        float4 xv = __ldg(&xr[h4]);
        acc += xv.x * w2s[(h4 * 4 + 0) * NC + c];
        acc += xv.y * w2s[(h4 * 4 + 1) * NC + c];
        acc += xv.z * w2s[(h4 * 4 + 2) * NC + c];
        acc += xv.w * w2s[(h4 * 4 + 3) * NC + c];
    }
    g_h[((long)r * NN + n) * NC + c] = acc;
}

// Layer-2 edge pass: acc2[dst] += h[rel, src].  4 threads per edge (16B each).
__global__ void k_edge2() {
    long gid = (long)blockIdx.x * blockDim.x + threadIdx.x;
    int e = (int)(gid >> 2);
    int s = (int)(gid & 3);
    if (e >= NE) return;
    int row = g_rowidx[e];
    int dst = g_dst[e];
    const float4* hp = (const float4*)(g_h + (long)row * NC);
    float4 v = __ldg(&hp[s]);
    red_add_v4(g_acc2 + (long)dst * NC + s * 4, v);
}

// out = log_softmax(acc2 + x @ root2 + b2)
__global__ void k_final(const float* __restrict__ root2, const float* __restrict__ b2,
                        float* __restrict__ out) {
    __shared__ float r2s[NH * NC];  // 4 KB
    for (int i = threadIdx.x; i < NH * NC; i += blockDim.x) r2s[i] = root2[i];
    __syncthreads();

    int c = threadIdx.x & 15;
    int n = blockIdx.x * 16 + (threadIdx.x >> 4);
    if (n >= NN) return;

    const float4* xr = (const float4*)(g_x + (long)n * NH);
    float acc = g_acc2[(long)n * NC + c] + b2[c];
#pragma unroll
    for (int h4 = 0; h4 < NH / 4; h4++) {
        float4 xv = __ldg(&xr[h4]);
        acc += xv.x * r2s[(h4 * 4 + 0) * NC + c];
        acc += xv.y * r2s[(h4 * 4 + 1) * NC + c];
        acc += xv.z * r2s[(h4 * 4 + 2) * NC + c];
        acc += xv.w * r2s[(h4 * 4 + 3) * NC + c];
    }

    // log_softmax across the 16 lanes of this half-warp
    unsigned mask = 0xFFFFu << (threadIdx.x & 16);
    float m = acc;
#pragma unroll
    for (int d = 8; d >= 1; d >>= 1) m = fmaxf(m, __shfl_xor_sync(mask, m, d));
    float ex = expf(acc - m);
    float sum = ex;
#pragma unroll
    for (int d = 8; d >= 1; d >>= 1) sum += __shfl_xor_sync(mask, sum, d);
    out[(long)n * NC + c] = acc - m - logf(sum);
}

extern "C" void kernel_launch(void* const* d_in, const int* in_sizes, int n_in,
                              void* d_out, int out_size) {
    const void*  edge_index = d_in[0];
    const void*  edge_type  = d_in[1];
    const float* W1         = (const float*)d_in[2];
    const float* root1      = (const float*)d_in[3];
    const float* b1         = (const float*)d_in[4];
    const float* W2         = (const float*)d_in[5];
    const float* root2      = (const float*)d_in[6];
    const float* b2         = (const float*)d_in[7];
    float* out = (float*)d_out;

    k_detect<<<1, 1>>>(edge_index);
    k_convert<<<(NE + 255) / 256, 256>>>(edge_index, edge_type);
    k_init<<<(NN * NH + 255) / 256, 256>>>(root1, b1);
    k_edge1<<<(int)(((long)NE * 16 + 255) / 256), 256>>>(W1);
    k_relu<<<(NN * NH + 255) / 256, 256>>>();
    {
        dim3 grid((NN + 15) / 16, NR);
        k_h<<<grid, 256>>>(W2);
    }
    k_edge2<<<(int)(((long)NE * 4 + 255) / 256), 256>>>();
    k_final<<<(NN + 15) / 16, 256>>>(root2, b2, out);
}